// round 12
// baseline (speedup 1.0000x reference)
#include <cuda_runtime.h>

// Problem: B=4, C=64, H=128, W=128, N=16, R=4, P=36
#define NPLANES (4*64)
#define PLANE   (128*128)
#define TOTAL   (4*64*128*128)
#define LOG2E   1.4426950408889634f
#define LN2     0.6931471805599453f

typedef unsigned long long ull;

__device__ float g_xT[TOTAL];                   // x transposed (h<->w) per plane
__device__ float g_scr[1024 * 20480 + 256];     // per (seq,l): [dl,du interleaved 128 | B 16 | C 16]
__device__ float g_y[1024 * 128 * 64];          // y[seq][l][c]

__device__ __forceinline__ float ex2f(float v) {
    float r; asm("ex2.approx.ftz.f32 %0, %1;" : "=f"(r) : "f"(v)); return r;
}
__device__ __forceinline__ float lg2f(float v) {
    float r; asm("lg2.approx.f32 %0, %1;" : "=f"(r) : "f"(v)); return r;
}
__device__ __forceinline__ ull pk(float a, float b) {
    ull r; asm("mov.b64 %0, {%1,%2};" : "=l"(r) : "f"(a), "f"(b)); return r;
}
__device__ __forceinline__ float2 upk(ull v) {
    float2 r; asm("mov.b64 {%0,%1}, %2;" : "=f"(r.x), "=f"(r.y) : "l"(v)); return r;
}
__device__ __forceinline__ ull fma2(ull a, ull b, ull c) {
    ull d; asm("fma.rn.f32x2 %0, %1, %2, %3;" : "=l"(d) : "l"(a), "l"(b), "l"(c)); return d;
}
__device__ __forceinline__ ull mul2(ull a, ull b) {
    ull d; asm("mul.rn.f32x2 %0, %1, %2;" : "=l"(d) : "l"(a), "l"(b)); return d;
}

// ---------------- transpose x -> g_xT : float4 both sides, plane-split ----------------
__global__ void transpose_kernel(const float* __restrict__ x, int z0) {
    __shared__ float tile[32][36];
    int plane = z0 + blockIdx.z;
    const float* src = x + plane * PLANE;
    float* dst = g_xT + plane * PLANE;
    int h0 = blockIdx.x * 32, w0 = blockIdx.y * 32;
    int tx = threadIdx.x, ty = threadIdx.y;
    float4 v = *reinterpret_cast<const float4*>(src + (h0 + ty) * 128 + w0 + tx * 4);
    tile[tx * 4 + 0][ty] = v.x;
    tile[tx * 4 + 1][ty] = v.y;
    tile[tx * 4 + 2][ty] = v.z;
    tile[tx * 4 + 3][ty] = v.w;
    __syncthreads();
    float4 o = *reinterpret_cast<const float4*>(&tile[ty][tx * 4]);
    *reinterpret_cast<float4*>(dst + (w0 + ty) * 128 + h0 + tx * 4) = o;
}

// ---------------- proj v3: 256 thr, 2 thr/token, u kept in regs, no spills ----------------
__global__ void __launch_bounds__(256, 3)
proj_kernel(const float* __restrict__ x,
            const float* __restrict__ x_proj_w,
            const float* __restrict__ dt_proj_w,
            const float* __restrict__ dt_proj_b)
{
    __shared__ float sW[64 * 40];     // [c][p] c-major
    __shared__ float sP[128 * 42];    // proj outputs [l][p] pad 42
    __shared__ float sdtw[256];
    __shared__ float sdtb[64];
    const int tid = threadIdx.x;
    const int l  = tid & 127;
    const int ph = tid >> 7;          // 0: outputs p 0..17, 1: p 18..35
    const int seq = blockIdx.x;
    const int dir = seq >> 9, sq = seq & 511, b = sq >> 7, row = sq & 127;
    const float* in = dir ? g_xT : x;
    const int base = (b * 64 * 128 + row) * 128;

    for (int idx = tid; idx < 36 * 64; idx += 256) {
        int p = idx >> 6, c = idx & 63;
        sW[c * 40 + p] = x_proj_w[idx];
    }
    sdtw[tid] = dt_proj_w[tid];
    if (tid < 64) sdtb[tid] = dt_proj_b[tid];
    __syncthreads();

    // ---- GEMM: 18 outputs (9 f32x2) per thread; capture own channel-half of u ----
    const int p0 = ph * 18;
    ull a2[9];
#pragma unroll
    for (int j = 0; j < 9; j++) a2[j] = 0ull;
    float ur[32];
#pragma unroll
    for (int i = 0; i < 64; i++) {
        int c = (ph * 32 + i) & 63;          // first 32 iters = own half
        float uc = in[base + c * 16384 + l]; // coalesced over l
        if (i < 32) ur[i] = uc;              // static index -> registers
        ull U2 = pk(uc, uc);
#pragma unroll
        for (int j = 0; j < 9; j++) {
            float2 w2 = *reinterpret_cast<const float2*>(&sW[c * 40 + p0 + 2 * j]);  // broadcast
            a2[j] = fma2(U2, pk(w2.x, w2.y), a2[j]);
        }
    }
#pragma unroll
    for (int j = 0; j < 9; j++)
        *reinterpret_cast<float2*>(&sP[l * 42 + p0 + 2 * j]) = upk(a2[j]);
    __syncthreads();

    // ---- phase 2: softplus for own 32 channels + scratch writeout ----
    float* srow = g_scr + (size_t)seq * 20480 + l * 160;
    float2 dta = *reinterpret_cast<const float2*>(&sP[l * 42 + 0]);
    float2 dtb2 = *reinterpret_cast<const float2*>(&sP[l * 42 + 2]);
    const float d0 = dta.x, d1 = dta.y, d2 = dtb2.x, d3 = dtb2.y;

#pragma unroll
    for (int k = 0; k < 32; k += 2) {
        float spv[2];
#pragma unroll
        for (int q = 0; q < 2; q++) {
            int dd = ph * 32 + k + q;
            float4 w4 = *reinterpret_cast<const float4*>(&sdtw[dd * 4]);  // broadcast
            float raw = sdtb[dd];
            raw = fmaf(d0, w4.x, raw);
            raw = fmaf(d1, w4.y, raw);
            raw = fmaf(d2, w4.z, raw);
            raw = fmaf(d3, w4.w, raw);
            float e = ex2f(raw * LOG2E);
            spv[q] = (raw > 20.0f) ? raw : lg2f(1.0f + e) * LN2;
        }
        *reinterpret_cast<float4*>(&srow[ph * 64 + 2 * k]) =
            make_float4(spv[0], spv[0] * ur[k], spv[1], spv[1] * ur[k + 1]);
    }
    // B (ph=0) / C (ph=1) copy from sP
    {
        int src_off = 4 + ph * 16;           // B at p 4..19, C at p 20..35
        int dst_off = 128 + ph * 16;
#pragma unroll
        for (int q = 0; q < 4; q++) {
            float v0 = sP[l * 42 + src_off + q * 4 + 0];
            float v1 = sP[l * 42 + src_off + q * 4 + 1];
            float v2 = sP[l * 42 + src_off + q * 4 + 2];
            float v3 = sP[l * 42 + src_off + q * 4 + 3];
            *reinterpret_cast<float4*>(&srow[dst_off + q * 4]) = make_float4(v0, v1, v2, v3);
        }
    }
}

// ---------------- selective scan: zero smem, 8 CTAs/SM (single wave), f32x2 math ----------------
__global__ void __launch_bounds__(128, 8)
scan_kernel(const float* __restrict__ A_log)
{
    const int tid = threadIdx.x;
    const int seq = blockIdx.x;
    const int d = tid >> 1, half = tid & 1, n0 = half * 8;
    ull A2[4];
#pragma unroll
    for (int j = 0; j < 4; j++) {
        float g0 = -__expf(__ldg(&A_log[d * 16 + n0 + 2 * j + 0])) * LOG2E;
        float g1 = -__expf(__ldg(&A_log[d * 16 + n0 + 2 * j + 1])) * LOG2E;
        A2[j] = pk(g0, g1);
    }

    const float* p = g_scr + (size_t)seq * 20480;
    float* yout = g_y + (size_t)seq * 8192;

    ull h0 = 0ull, h1 = 0ull, h2 = 0ull, h3 = 0ull;

#pragma unroll 2
    for (int l = 0; l < 128; l++) {
        const float* pr = p + l * 160;
        float2 dldu   = __ldg(reinterpret_cast<const float2*>(&pr[2 * d]));
        ulonglong2 Ba = __ldg(reinterpret_cast<const ulonglong2*>(&pr[128 + n0]));
        ulonglong2 Bb = __ldg(reinterpret_cast<const ulonglong2*>(&pr[132 + n0]));
        ulonglong2 Ca = __ldg(reinterpret_cast<const ulonglong2*>(&pr[144 + n0]));
        ulonglong2 Cb = __ldg(reinterpret_cast<const ulonglong2*>(&pr[148 + n0]));

        ull DL2 = pk(dldu.x, dldu.x);
        ull DU2 = pk(dldu.y, dldu.y);
        float2 g0 = upk(mul2(DL2, A2[0]));
        float2 g1 = upk(mul2(DL2, A2[1]));
        float2 g2 = upk(mul2(DL2, A2[2]));
        float2 g3 = upk(mul2(DL2, A2[3]));
        h0 = fma2(pk(ex2f(g0.x), ex2f(g0.y)), h0, mul2(DU2, Ba.x));
        h1 = fma2(pk(ex2f(g1.x), ex2f(g1.y)), h1, mul2(DU2, Ba.y));
        h2 = fma2(pk(ex2f(g2.x), ex2f(g2.y)), h2, mul2(DU2, Bb.x));
        h3 = fma2(pk(ex2f(g3.x), ex2f(g3.y)), h3, mul2(DU2, Bb.y));
        ull T0 = mul2(h0, Ca.x);
        ull T1 = mul2(h1, Ca.y);
        T0 = fma2(h2, Cb.x, T0);
        T1 = fma2(h3, Cb.y, T1);
        float2 ta = upk(T0);
        float2 tb = upk(T1);
        float t = (ta.x + ta.y) + (tb.x + tb.y);
        t += __shfl_xor_sync(0xffffffffu, t, 1);
        if (half == 0) yout[l * 64 + d] = t;
    }
}

// ---------------- combine: out = yh + yv + 2*x*D ----------------
__global__ void __launch_bounds__(256)
combine_kernel(const float* __restrict__ x,
               const float* __restrict__ Dvec,
               float* __restrict__ out)
{
    __shared__ float th[128 * 37];
    __shared__ float tv[128 * 37];
    const int tid = threadIdx.x;
    const int bh = blockIdx.x >> 1;
    const int c0 = (blockIdx.x & 1) * 32;
    const int b = bh >> 7, h = bh & 127;
    const int seq_h = b * 128 + h;

#pragma unroll
    for (int r = 0; r < 4; r++) {
        int idx = r * 256 + tid;            // 0..1023
        int w = idx >> 3, cc = (idx & 7) * 4;
        float4 vh = *reinterpret_cast<const float4*>(&g_y[(size_t)seq_h * 8192 + w * 64 + c0 + cc]);
        th[w * 37 + cc + 0] = vh.x;
        th[w * 37 + cc + 1] = vh.y;
        th[w * 37 + cc + 2] = vh.z;
        th[w * 37 + cc + 3] = vh.w;
        int seq_v = 512 + b * 128 + w;
        float4 vv = *reinterpret_cast<const float4*>(&g_y[(size_t)seq_v * 8192 + h * 64 + c0 + cc]);
        tv[w * 37 + cc + 0] = vv.x;
        tv[w * 37 + cc + 1] = vv.y;
        tv[w * 37 + cc + 2] = vv.z;
        tv[w * 37 + cc + 3] = vv.w;
    }
    __syncthreads();

    const float* xb = x + b * 1048576 + h * 128;
    float* ob = out + b * 1048576 + h * 128;
#pragma unroll
    for (int r = 0; r < 16; r++) {
        int idx = r * 256 + tid;            // 0..4095
        int c = idx >> 7, w = idx & 127;
        int cg = c0 + c;
        float xv = xb[cg * 16384 + w];
        float val = th[w * 37 + c] + tv[w * 37 + c] + 2.0f * xv * __ldg(&Dvec[cg]);
        ob[cg * 16384 + w] = val;
    }
}

extern "C" void kernel_launch(void* const* d_in, const int* in_sizes, int n_in,
                              void* d_out, int out_size) {
    const float* x     = (const float*)d_in[0];
    const float* A_log = (const float*)d_in[1];
    const float* Dv    = (const float*)d_in[2];
    const float* xpw   = (const float*)d_in[3];
    const float* dtw   = (const float*)d_in[4];
    const float* dtb   = (const float*)d_in[5];
    float* out = (float*)d_out;

    dim3 tb(8, 32);
    dim3 tgA(4, 4, 86), tgB(4, 4, 85);
    // Order: T1(0), T2(1), T3(2), P(3 <- profiled), S(4), C(5)
    transpose_kernel<<<tgA, tb>>>(x, 0);
    transpose_kernel<<<tgB, tb>>>(x, 86);
    transpose_kernel<<<tgB, tb>>>(x, 171);
    proj_kernel<<<1024, 256>>>(x, xpw, dtw, dtb);
    scan_kernel<<<1024, 128>>>(A_log);
    combine_kernel<<<1024, 256>>>(x, Dv, out);
}